// round 15
// baseline (speedup 1.0000x reference)
#include <cuda_runtime.h>
#include <cstdint>
#include <math.h>

#define Bb 128
#define Tt 25
#define Ee 512
#define Hh 1024
#define Vv 10000
#define Ff 2048

// ---------------- device scratch ----------------
__device__ float g_wbuf[36331520];     // tf32-rounded weights + embedding
__device__ float g_featin[Bb*Ff];
__device__ float g_feat[Bb*Hh];
__device__ float g_prefeat[Bb*4096];   // feat @ W0i[512:1536] + bias0i
__device__ float g_pre0[Tt*Bb*4096];   // full input-part of layer0 gates
__device__ float g_c0[Bb*Hh];
__device__ float g_c1[Bb*Hh];
__device__ float g_comb1[Bb*2048];     // [h0 | h1]
__device__ float g_hs[Tt*Bb*Hh];
__device__ float g_part[128*4096];     // k-split partial tiles
__device__ float g_bias0i[4096];
__device__ float g_bias1i[4096];
__device__ unsigned g_bgrp[8*64];      // barrier group counters, 256B stride
__device__ unsigned g_barc;            // barrier root
__device__ unsigned g_hbar;            // head kernel barrier

// wbuf offsets (floats)
#define OF_WP   0
#define OF_W0I  2097152      /* 2560x4096 interleaved */
#define OF_W1I  12582912     /* 2048x4096 interleaved */
#define OF_WOUT 20971520     /* 1024x10000 row-major -> ends at 31211520 */
#define OF_EMB  31211520     /* 10000x512 rounded embedding */

__device__ __forceinline__ uint32_t f2tf(float x){
    uint32_t u; asm("cvt.rna.tf32.f32 %0, %1;" : "=r"(u) : "f"(x)); return u;
}
__device__ __forceinline__ float roundtf(float x){ return __uint_as_float(f2tf(x)); }
__device__ __forceinline__ float sigf(float x){ return 1.0f/(1.0f + expf(-x)); }

__device__ __forceinline__ void cp16(float* sdst, const float* gsrc){
    uint32_t s = (uint32_t)__cvta_generic_to_shared(sdst);
    asm volatile("cp.async.cg.shared.global [%0], [%1], 16;\n" :: "r"(s), "l"(gsrc));
}
__device__ __forceinline__ void cp16p(float* sdst, const float* gsrc, bool pred){
    uint32_t s = (uint32_t)__cvta_generic_to_shared(sdst);
    int sz = pred ? 16 : 0;
    asm volatile("cp.async.cg.shared.global [%0], [%1], 16, %2;\n" :: "r"(s), "l"(gsrc), "r"(sz));
}
__device__ __forceinline__ void cp_commit(){ asm volatile("cp.async.commit_group;\n"); }
__device__ __forceinline__ void cp_wait1(){ asm volatile("cp.async.wait_group 1;\n"); }
__device__ __forceinline__ void cp_wait2(){ asm volatile("cp.async.wait_group 2;\n"); }
__device__ __forceinline__ void cp_wait0(){ asm volatile("cp.async.wait_group 0;\n"); }

// ---------------- one-shot convert / pack / zero kernel ----------------
#define S_FEAT 65536
#define S_WP   524288
#define S_WOUT 2560000
#define S_EMB  1280000
#define S_W0I  2621440
#define S_W1I  2097152
#define S_B    1024
#define S_Z    (32768+32768+65536+3+512)
#define CVT_TOTAL (S_FEAT+S_WP+S_WOUT+S_EMB+S_W0I+S_W1I+2*S_B+S_Z)

__global__ void cvt_all(
    const float* __restrict__ features, const float* __restrict__ Wp,
    const float* __restrict__ Wout, const float* __restrict__ emb,
    const float* __restrict__ Wf0, const float* __restrict__ Wi0,
    const float* __restrict__ Wo0, const float* __restrict__ Wg0,
    const float* __restrict__ Wf1, const float* __restrict__ Wi1,
    const float* __restrict__ Wo1, const float* __restrict__ Wg1,
    const float* __restrict__ bf0, const float* __restrict__ bi0,
    const float* __restrict__ bo0, const float* __restrict__ bg0,
    const float* __restrict__ bf1, const float* __restrict__ bi1,
    const float* __restrict__ bo1, const float* __restrict__ bg1)
{
    int i = blockIdx.x*blockDim.x + threadIdx.x;
    if (i >= CVT_TOTAL) return;
    if (i < S_FEAT){
        float4 v = reinterpret_cast<const float4*>(features)[i];
        v.x=roundtf(v.x); v.y=roundtf(v.y); v.z=roundtf(v.z); v.w=roundtf(v.w);
        reinterpret_cast<float4*>(g_featin)[i] = v; return;
    }
    i -= S_FEAT;
    if (i < S_WP){
        float4 v = reinterpret_cast<const float4*>(Wp)[i];
        v.x=roundtf(v.x); v.y=roundtf(v.y); v.z=roundtf(v.z); v.w=roundtf(v.w);
        reinterpret_cast<float4*>(g_wbuf + OF_WP)[i] = v; return;
    }
    i -= S_WP;
    if (i < S_WOUT){
        float4 v = reinterpret_cast<const float4*>(Wout)[i];
        v.x=roundtf(v.x); v.y=roundtf(v.y); v.z=roundtf(v.z); v.w=roundtf(v.w);
        reinterpret_cast<float4*>(g_wbuf + OF_WOUT)[i] = v; return;
    }
    i -= S_WOUT;
    if (i < S_EMB){
        float4 v = reinterpret_cast<const float4*>(emb)[i];
        v.x=roundtf(v.x); v.y=roundtf(v.y); v.z=roundtf(v.z); v.w=roundtf(v.w);
        reinterpret_cast<float4*>(g_wbuf + OF_EMB)[i] = v; return;
    }
    i -= S_EMB;
    if (i < S_W0I){
        int k = i >> 10, h = i & 1023;
        int s = k*1024 + h;
        float4 v;
        v.x = roundtf(Wf0[s]); v.y = roundtf(Wi0[s]);
        v.z = roundtf(Wo0[s]); v.w = roundtf(Wg0[s]);
        reinterpret_cast<float4*>(g_wbuf + OF_W0I)[(size_t)k*1024 + h] = v; return;
    }
    i -= S_W0I;
    if (i < S_W1I){
        int k = i >> 10, h = i & 1023;
        int s = k*1024 + h;
        float4 v;
        v.x = roundtf(Wf1[s]); v.y = roundtf(Wi1[s]);
        v.z = roundtf(Wo1[s]); v.w = roundtf(Wg1[s]);
        reinterpret_cast<float4*>(g_wbuf + OF_W1I)[(size_t)k*1024 + h] = v; return;
    }
    i -= S_W1I;
    if (i < S_B){
        float4 v; v.x=bf0[i]; v.y=bi0[i]; v.z=bo0[i]; v.w=bg0[i];
        reinterpret_cast<float4*>(g_bias0i)[i] = v; return;
    }
    i -= S_B;
    if (i < S_B){
        float4 v; v.x=bf1[i]; v.y=bi1[i]; v.z=bo1[i]; v.w=bg1[i];
        reinterpret_cast<float4*>(g_bias1i)[i] = v; return;
    }
    i -= S_B;
    {
        float4 z = make_float4(0.f,0.f,0.f,0.f);
        if (i < 32768){ reinterpret_cast<float4*>(g_c0)[i] = z; return; }
        i -= 32768;
        if (i < 32768){ reinterpret_cast<float4*>(g_c1)[i] = z; return; }
        i -= 32768;
        if (i < 65536){ reinterpret_cast<float4*>(g_comb1)[i] = z; return; }
        i -= 65536;
        if (i == 0){ g_barc = 0u; return; }
        if (i == 1){ g_hbar = 0u; return; }
        if (i == 2) return;
        g_bgrp[i-3] = 0u;
    }
}

// ---------------- 128x128x16 TF32 HMMA GEMM body (head/pre0/out) ----------
#define MODE_LEAKY 1
#define MODE_REMAP 4

struct SmemGemm {
    float As[4][128][20];
    float Ws[4][16][136];
};

__device__ __forceinline__ void gemm128_body(
    const float* __restrict__ A, int lda, int K,
    const float* __restrict__ W, int ldw,
    const float* __restrict__ bias, const float* __restrict__ rowext,
    float* __restrict__ C, int ldc, int N, int mode,
    int n0, int m0,
    const int* __restrict__ gtok, const float* __restrict__ embW,
    SmemGemm& s)
{
    const int tid  = threadIdx.x;
    const int lane = tid & 31, warp = tid >> 5;
    const int wm = warp & 3, wn = warp >> 2;      // warp tile 32x64
    const int g  = lane >> 2, tg = lane & 3;

    const int ar = tid >> 1,  ac = (tid & 1) * 8;
    const int wr = tid >> 4,  wc = (tid & 15) * 8;
    const bool wp0 = (n0 + wc)     < N;
    const bool wp1 = (n0 + wc + 4) < N;
    const float* asrc;
    if (gtok){
        int t = m0 >> 7;
        int tok = gtok[ar*Tt + t];
        asrc = embW + (size_t)tok*Ee + ac;
    } else {
        asrc = A + (size_t)(m0+ar)*lda + ac;
    }
    const float* wsrc = W + (size_t)wr*ldw + n0 + wc;

    float acc[2][8][4];
    #pragma unroll
    for (int mi=0;mi<2;mi++)
        #pragma unroll
        for (int ni=0;ni<8;ni++)
            #pragma unroll
            for (int j=0;j<4;j++) acc[mi][ni][j]=0.f;

    const int nk = K >> 4;
    #pragma unroll
    for (int st2=0; st2<3; ++st2){
        cp16 (&s.As[st2][ar][ac],   asrc + st2*16);
        cp16 (&s.As[st2][ar][ac+4], asrc + st2*16 + 4);
        cp16p(&s.Ws[st2][wr][wc],   wp0 ? (wsrc + (size_t)(st2*16)*ldw)     : W, wp0);
        cp16p(&s.Ws[st2][wr][wc+4], wp1 ? (wsrc + (size_t)(st2*16)*ldw + 4) : W, wp1);
        cp_commit();
    }

    for (int kt=0; kt<nk; ++kt){
        cp_wait2();
        __syncthreads();
        int kn = kt + 3;
        if (kn < nk){
            int sn = kn & 3;
            cp16 (&s.As[sn][ar][ac],   asrc + kn*16);
            cp16 (&s.As[sn][ar][ac+4], asrc + kn*16 + 4);
            cp16p(&s.Ws[sn][wr][wc],   wp0 ? (wsrc + (size_t)(kn*16)*ldw)     : W, wp0);
            cp16p(&s.Ws[sn][wr][wc+4], wp1 ? (wsrc + (size_t)(kn*16)*ldw + 4) : W, wp1);
        }
        cp_commit();
        const int st = kt & 3;
        #pragma unroll
        for (int kk=0; kk<2; ++kk){
            const int kc = kk*8 + tg;
            uint32_t afr[2][4];
            #pragma unroll
            for (int mi=0; mi<2; ++mi){
                const int rr = wm*32 + mi*16 + g;
                afr[mi][0] = __float_as_uint(s.As[st][rr  ][kc  ]);
                afr[mi][1] = __float_as_uint(s.As[st][rr+8][kc  ]);
                afr[mi][2] = __float_as_uint(s.As[st][rr  ][kc+4]);
                afr[mi][3] = __float_as_uint(s.As[st][rr+8][kc+4]);
            }
            #pragma unroll
            for (int ni=0; ni<8; ++ni){
                const int nc = wn*64 + ni*8 + g;
                uint32_t b0 = __float_as_uint(s.Ws[st][kc  ][nc]);
                uint32_t b1 = __float_as_uint(s.Ws[st][kc+4][nc]);
                #pragma unroll
                for (int mi=0; mi<2; ++mi){
                    asm volatile(
                        "mma.sync.aligned.m16n8k8.row.col.f32.tf32.tf32.f32 "
                        "{%0,%1,%2,%3}, {%4,%5,%6,%7}, {%8,%9}, {%0,%1,%2,%3};\n"
                        : "+f"(acc[mi][ni][0]), "+f"(acc[mi][ni][1]),
                          "+f"(acc[mi][ni][2]), "+f"(acc[mi][ni][3])
                        : "r"(afr[mi][0]), "r"(afr[mi][1]),
                          "r"(afr[mi][2]), "r"(afr[mi][3]), "r"(b0), "r"(b1));
                }
            }
        }
    }
    cp_wait0();
    __syncthreads();

    #pragma unroll
    for (int mi=0; mi<2; ++mi){
        const int grow0 = m0 + wm*32 + mi*16 + g;
        const int grow1 = grow0 + 8;
        size_t drow0, drow1;
        if (mode & MODE_REMAP){
            drow0 = (size_t)((grow0 & 127)*Tt + (grow0 >> 7));
            drow1 = (size_t)((grow1 & 127)*Tt + (grow1 >> 7));
        } else { drow0 = (size_t)grow0; drow1 = (size_t)grow1; }
        float* C0 = C + drow0*ldc;
        float* C1 = C + drow1*ldc;
        #pragma unroll
        for (int ni=0; ni<8; ++ni){
            const int gcol = n0 + wn*64 + ni*8 + 2*tg;
            if (gcol >= N) continue;
            float v00=acc[mi][ni][0], v01=acc[mi][ni][1];
            float v10=acc[mi][ni][2], v11=acc[mi][ni][3];
            if (bias){
                float b0v = bias[gcol], b1v = bias[gcol+1];
                v00+=b0v; v01+=b1v; v10+=b0v; v11+=b1v;
            }
            if (rowext){
                const float* r0 = rowext + (size_t)(grow0 & 127)*4096;
                const float* r1 = rowext + (size_t)(grow1 & 127)*4096;
                v00 += r0[gcol]; v01 += r0[gcol+1];
                v10 += r1[gcol]; v11 += r1[gcol+1];
            }
            if (mode & MODE_LEAKY){
                v00 = roundtf(v00 > 0.f ? v00 : 0.01f*v00);
                v01 = roundtf(v01 > 0.f ? v01 : 0.01f*v01);
                v10 = roundtf(v10 > 0.f ? v10 : 0.01f*v10);
                v11 = roundtf(v11 > 0.f ? v11 : 0.01f*v11);
            }
            C0[gcol] = v00; C0[gcol+1] = v01;
            C1[gcol] = v10; C1[gcol+1] = v11;
        }
    }
}

__global__ __launch_bounds__(256) void gemm128k(
    const float* __restrict__ A, int lda, int K,
    const float* __restrict__ W, int ldw,
    const float* __restrict__ bias, const float* __restrict__ rowext,
    float* __restrict__ C, int ldc, int N, int mode,
    const int* __restrict__ gtok, const float* __restrict__ embW)
{
    __shared__ SmemGemm s;
    gemm128_body(A, lda, K, W, ldw, bias, rowext, C, ldc, N, mode,
                 blockIdx.x*128, blockIdx.y*128, gtok, embW, s);
}

__global__ __launch_bounds__(256) void head_kernel(const float* __restrict__ bp)
{
    __shared__ SmemGemm s;
    const int cta = blockIdx.x;
    if (cta < 8){
        gemm128_body(g_featin, Ff, Ff, g_wbuf + OF_WP, Hh, bp, nullptr,
                     g_feat, Hh, Hh, MODE_LEAKY, cta*128, 0, nullptr, nullptr, s);
    }
    __syncthreads();
    if (threadIdx.x == 0){
        __threadfence();
        atomicAdd(&g_hbar, 1u);
        unsigned v;
        do {
            asm volatile("ld.acquire.gpu.u32 %0, [%1];" : "=r"(v) : "l"(&g_hbar) : "memory");
            if (v < 40u) __nanosleep(200);
        } while (v < 40u);
    }
    __syncthreads();
    if (cta >= 8){
        gemm128_body(g_feat, Hh, Hh, g_wbuf + OF_W0I + (size_t)512*4096, 4096,
                     g_bias0i, nullptr, g_prefeat, 4096, 4096, 0,
                     (cta-8)*128, 0, nullptr, nullptr, s);
    }
}

// ---------------- persistent recurrence: BK=32, 3-stage ----------------
#define NCTA 256u

__device__ __forceinline__ void gridbar(unsigned &ep, int cta){
    __syncthreads();
    ep += 1;
    if (threadIdx.x == 0){
        __threadfence();
        const int grp = cta >> 5;                 // 8 groups of 32
        unsigned* gc = &g_bgrp[grp*64];
        atomicAdd(gc, 1u);
        unsigned v;
        if ((cta & 31) == 0){
            do {
                asm volatile("ld.acquire.gpu.u32 %0, [%1];" : "=r"(v) : "l"(gc) : "memory");
                if (v < ep*32u) __nanosleep(128);
            } while (v < ep*32u);
            __threadfence();
            atomicAdd(&g_barc, 1u);
        }
        do {
            asm volatile("ld.acquire.gpu.u32 %0, [%1];" : "=r"(v) : "l"(&g_barc) : "memory");
            if (v < ep*8u) __nanosleep(128);
        } while (v < ep*8u);
    }
    __syncthreads();
}

// 64x64 tile, BK=32, 3-stage pipeline. nk = number of 32-wide k-iters.
__device__ __forceinline__ void gemm_tile_bk32(
    const float* __restrict__ A, int lda,
    const float* __restrict__ W, int ldw,
    int m0, int n0, int kbase, int nk,
    float (&As)[3][64][36], float (&Ws)[3][32][72],
    float acc[4][4])
{
    const int tid  = threadIdx.x;
    const int lane = tid & 31, warp = tid >> 5;
    const int wm = warp & 3, wn = warp >> 2;
    const int g  = lane >> 2, tg = lane & 3;
    // A tile 64x32: 2 float4 per thread
    const int ar = tid >> 2,  ac = (tid & 3) * 8;
    // W tile 32x64: 2 float4 per thread
    const int wr = tid >> 3,  wc = (tid & 7) * 8;
    const float* asrc = A + (size_t)(m0+ar)*lda + kbase + ac;
    const float* wsrc = W + (size_t)(kbase+wr)*ldw + n0 + wc;

    #pragma unroll
    for (int i=0;i<4;i++){
        #pragma unroll
        for (int j=0;j<4;j++) acc[i][j]=0.f;
    }

    // prologue: fill stages 0,1
    #pragma unroll
    for (int st2=0; st2<2; ++st2){
        cp16(&As[st2][ar][ac],   asrc + st2*32);
        cp16(&As[st2][ar][ac+4], asrc + st2*32 + 4);
        cp16(&Ws[st2][wr][wc],   wsrc + (size_t)(st2*32)*ldw);
        cp16(&Ws[st2][wr][wc+4], wsrc + (size_t)(st2*32)*ldw + 4);
        cp_commit();
    }

    for (int kt=0; kt<nk; ++kt){
        cp_wait1();
        __syncthreads();
        int kn = kt + 2;
        if (kn < nk){
            int sn = kn % 3;
            cp16(&As[sn][ar][ac],   asrc + kn*32);
            cp16(&As[sn][ar][ac+4], asrc + kn*32 + 4);
            cp16(&Ws[sn][wr][wc],   wsrc + (size_t)(kn*32)*ldw);
            cp16(&Ws[sn][wr][wc+4], wsrc + (size_t)(kn*32)*ldw + 4);
        }
        cp_commit();
        const int st = kt % 3;
        const int rr = wm*16 + g;
        #pragma unroll
        for (int kk=0; kk<4; ++kk){
            const int kc = kk*8 + tg;
            uint32_t a0 = __float_as_uint(As[st][rr  ][kc  ]);
            uint32_t a1 = __float_as_uint(As[st][rr+8][kc  ]);
            uint32_t a2 = __float_as_uint(As[st][rr  ][kc+4]);
            uint32_t a3 = __float_as_uint(As[st][rr+8][kc+4]);
            #pragma unroll
            for (int ni=0; ni<4; ++ni){
                const int nc = wn*32 + ni*8 + g;
                uint32_t b0 = __float_as_uint(Ws[st][kc  ][nc]);
                uint32_t b1 = __float_as_uint(Ws[st][kc+4][nc]);
                asm volatile(
                    "mma.sync.aligned.m16n8k8.row.col.f32.tf32.tf32.f32 "
                    "{%0,%1,%2,%3}, {%4,%5,%6,%7}, {%8,%9}, {%0,%1,%2,%3};\n"
                    : "+f"(acc[ni][0]), "+f"(acc[ni][1]),
                      "+f"(acc[ni][2]), "+f"(acc[ni][3])
                    : "r"(a0), "r"(a1), "r"(a2), "r"(a3), "r"(b0), "r"(b1));
            }
        }
    }
    cp_wait0();
    __syncthreads();
}

__device__ __forceinline__ void store_partial(float acc[4][4], int tile,
                                              int wm, int wn, int g, int tg)
{
    float* gp = g_part + (size_t)tile*4096;
    const int lr0 = wm*16 + g, lr1 = lr0 + 8;
    #pragma unroll
    for (int ni=0; ni<4; ++ni){
        const int lc = wn*32 + ni*8 + 2*tg;
        gp[lr0*64 + lc]   = acc[ni][0];
        gp[lr0*64 + lc+1] = acc[ni][1];
        gp[lr1*64 + lc]   = acc[ni][2];
        gp[lr1*64 + lc+1] = acc[ni][3];
    }
}

__device__ __forceinline__ void lstm_epi(float acc[4][4], int tile, int t,
    const float* rowext, const float* colext,
    float* cbuf, int hoff, bool write_hs,
    int m0, int n0, int nb, int wm, int wn, int g, int tg)
{
    const float* gp = g_part + (size_t)tile*4096;
    const int lr0 = wm*16 + g, lr1 = lr0 + 8;
    const int grow0 = m0 + lr0, grow1 = m0 + lr1;
    #pragma unroll
    for (int ni=0; ni<4; ++ni){
        const int lc = wn*32 + ni*8 + 2*tg;
        const int gcol = n0 + lc;
        float v00 = acc[ni][0] + gp[lr0*64 + lc];
        float v01 = acc[ni][1] + gp[lr0*64 + lc+1];
        float v10 = acc[ni][2] + gp[lr1*64 + lc];
        float v11 = acc[ni][3] + gp[lr1*64 + lc+1];
        if (rowext){
            v00 += rowext[(size_t)grow0*4096 + gcol];
            v01 += rowext[(size_t)grow0*4096 + gcol+1];
            v10 += rowext[(size_t)grow1*4096 + gcol];
            v11 += rowext[(size_t)grow1*4096 + gcol+1];
        } else {
            float b0 = colext[gcol], b1 = colext[gcol+1];
            v00+=b0; v01+=b1; v10+=b0; v11+=b1;
        }
        float p00 = __shfl_xor_sync(0xffffffffu, v00, 1);
        float p01 = __shfl_xor_sync(0xffffffffu, v01, 1);
        float p10 = __shfl_xor_sync(0xffffffffu, v10, 1);
        float p11 = __shfl_xor_sync(0xffffffffu, v11, 1);
        if ((tg & 1) == 0){
            const int h = nb*16 + wn*8 + ni*2 + (tg >> 1);
            {
                float f = sigf(v00), ii = sigf(v01);
                float o = sigf(p00), gg = tanhf(p01);
                float c = f*cbuf[grow0*1024 + h] + ii*gg;
                cbuf[grow0*1024 + h] = c;
                float hn = roundtf(o * tanhf(c));
                g_comb1[grow0*2048 + hoff + h] = hn;
                if (write_hs) g_hs[(size_t)t*(Bb*Hh) + grow0*1024 + h] = hn;
            }
            {
                float f = sigf(v10), ii = sigf(v11);
                float o = sigf(p10), gg = tanhf(p11);
                float c = f*cbuf[grow1*1024 + h] + ii*gg;
                cbuf[grow1*1024 + h] = c;
                float hn = roundtf(o * tanhf(c));
                g_comb1[grow1*2048 + hoff + h] = hn;
                if (write_hs) g_hs[(size_t)t*(Bb*Hh) + grow1*1024 + h] = hn;
            }
        }
    }
}

__global__ __launch_bounds__(256, 2) void lstm_persistent()
{
    __shared__ __align__(16) float As[3][64][36];
    __shared__ __align__(16) float Ws[3][32][72];

    const int cta  = blockIdx.x;
    const int ks   = cta & 1;
    const int tile = cta >> 1;
    const int mb   = tile & 1, nb = tile >> 1;
    const int m0   = mb*64,   n0 = nb*64;
    const int tid  = threadIdx.x;
    const int lane = tid & 31, warp = tid >> 5;
    const int wm = warp & 3, wn = warp >> 2;
    const int g  = lane >> 2, tg = lane & 3;

    const float* Wrec0 = g_wbuf + OF_W0I + (size_t)1536*4096;
    const float* W1    = g_wbuf + OF_W1I;

    unsigned ep = 0;
    float acc[4][4];

    for (int t = 0; t < Tt; ++t){
        gemm_tile_bk32(g_comb1, 2048, Wrec0, 4096, m0, n0, ks*512, 16, As, Ws, acc);
        if (ks == 1) store_partial(acc, tile, wm, wn, g, tg);
        gridbar(ep, cta);
        if (ks == 0)
            lstm_epi(acc, tile, t, g_pre0 + (size_t)t*(Bb*4096), nullptr,
                     g_c0, 0, false, m0, n0, nb, wm, wn, g, tg);
        gridbar(ep, cta);
        gemm_tile_bk32(g_comb1, 2048, W1, 4096, m0, n0, ks*1024, 32, As, Ws, acc);
        if (ks == 1) store_partial(acc, tile, wm, wn, g, tg);
        gridbar(ep, cta);
        if (ks == 0)
            lstm_epi(acc, tile, t, nullptr, g_bias1i,
                     g_c1, 1024, true, m0, n0, nb, wm, wn, g, tg);
        gridbar(ep, cta);
    }
}

// ---------------- host orchestration ----------------
extern "C" void kernel_launch(void* const* d_in, const int* in_sizes, int n_in,
                              void* d_out, int out_size)
{
    const int*   tokens    = (const int*)  d_in[0];
    const float* features  = (const float*)d_in[1];
    const float* embedding = (const float*)d_in[2];
    const float* Wp  = (const float*)d_in[3];
    const float* bp  = (const float*)d_in[4];
    const float* Wf0 = (const float*)d_in[5];  const float* bf0 = (const float*)d_in[6];
    const float* Wi0 = (const float*)d_in[7];  const float* bi0 = (const float*)d_in[8];
    const float* Wo0 = (const float*)d_in[9];  const float* bo0 = (const float*)d_in[10];
    const float* Wg0 = (const float*)d_in[11]; const float* bg0 = (const float*)d_in[12];
    const float* Wf1 = (const float*)d_in[13]; const float* bf1 = (const float*)d_in[14];
    const float* Wi1 = (const float*)d_in[15]; const float* bi1 = (const float*)d_in[16];
    const float* Wo1 = (const float*)d_in[17]; const float* bo1 = (const float*)d_in[18];
    const float* Wg1 = (const float*)d_in[19]; const float* bg1 = (const float*)d_in[20];
    const float* Wout = (const float*)d_in[21];
    const float* bout = (const float*)d_in[22];
    float* out = (float*)d_out;

    float *wb, *pre0, *prefeat, *hs;
    cudaGetSymbolAddress((void**)&wb,      g_wbuf);
    cudaGetSymbolAddress((void**)&pre0,    g_pre0);
    cudaGetSymbolAddress((void**)&prefeat, g_prefeat);
    cudaGetSymbolAddress((void**)&hs,      g_hs);

    // 1) convert + pack + zero (single launch)
    cvt_all<<<(CVT_TOTAL + 255)/256, 256>>>(features, Wp, Wout, embedding,
        Wf0, Wi0, Wo0, Wg0, Wf1, Wi1, Wo1, Wg1,
        bf0, bi0, bo0, bg0, bf1, bi1, bo1, bg1);

    // 2) head: feat projection + prefeat (fused, internal barrier)
    head_kernel<<<40, 256>>>(bp);

    // 3) pre0 = gather(emb) @ W0i[0:512,:] + prefeat[b]   (K=512)
    gemm128k<<<dim3(32,25), 256>>>(nullptr, 0, 512,
        wb + OF_W0I, 4096, nullptr, prefeat,
        pre0, 4096, 4096, 0, tokens, wb + OF_EMB);

    // 4) persistent 25-step recurrence, BK=32   <-- profiled slot
    lstm_persistent<<<NCTA, 256>>>();

    // 5) logits = hs @ Wout + bout, remap to [B,T,V]
    gemm128k<<<dim3(79,25), 256>>>(hs, Hh, Hh,
        wb + OF_WOUT, Vv, bout, nullptr, out, Vv, Vv, MODE_REMAP,
        nullptr, nullptr);
}

// round 16
// speedup vs baseline: 1.4595x; 1.4595x over previous
#include <cuda_runtime.h>
#include <cuda_fp16.h>
#include <cstdint>
#include <math.h>

#define Bb 128
#define Tt 25
#define Ee 512
#define Hh 1024
#define Vv 10000
#define Ff 2048

// ---------------- device scratch ----------------
__device__ __align__(16) __half g_wbufH[36331520]; // fp16 weights(+emb), k-pair packed
__device__ __align__(16) __half g_featinH[Bb*Ff];
__device__ __align__(16) __half g_featH[Bb*Hh];
__device__ __align__(16) __half g_comb1H[Bb*2048];  // [h0 | h1]
__device__ __align__(16) __half g_hsH[Tt*Bb*Hh];
__device__ float g_prefeat[Bb*4096];
__device__ float g_pre0[Tt*Bb*4096];
__device__ float g_c0[Bb*Hh];
__device__ float g_c1[Bb*Hh];
__device__ float g_part[128*4096];
__device__ float g_bias0i[4096];
__device__ float g_bias1i[4096];
__device__ unsigned g_bgrp[8*64];
__device__ unsigned g_barc;
__device__ unsigned g_hbar;

// wbufH offsets (halves; all even)
#define OF_WP   0            /* packed 1024x1024 u32  */
#define OF_W0I  2097152      /* packed 1280x4096 u32  */
#define OF_W1I  12582912     /* packed 1024x4096 u32  */
#define OF_WOUT 20971520     /* packed  512x10000 u32 */
#define OF_EMB  31211520     /* row-major half 10000x512 */

__device__ __forceinline__ float sigf(float x){ return 1.0f/(1.0f + expf(-x)); }
__device__ __forceinline__ uint32_t pack2h(float a, float b){
    uint32_t lo = (uint32_t)__half_as_ushort(__float2half_rn(a));
    uint32_t hi = (uint32_t)__half_as_ushort(__float2half_rn(b));
    return lo | (hi << 16);
}

__device__ __forceinline__ void cp16(void* sdst, const void* gsrc){
    uint32_t s = (uint32_t)__cvta_generic_to_shared(sdst);
    asm volatile("cp.async.cg.shared.global [%0], [%1], 16;\n" :: "r"(s), "l"(gsrc));
}
__device__ __forceinline__ void cp16p(void* sdst, const void* gsrc, bool pred){
    uint32_t s = (uint32_t)__cvta_generic_to_shared(sdst);
    int sz = pred ? 16 : 0;
    asm volatile("cp.async.cg.shared.global [%0], [%1], 16, %2;\n" :: "r"(s), "l"(gsrc), "r"(sz));
}
__device__ __forceinline__ void cp_commit(){ asm volatile("cp.async.commit_group;\n"); }
__device__ __forceinline__ void cp_wait2(){ asm volatile("cp.async.wait_group 2;\n"); }
__device__ __forceinline__ void cp_wait0(){ asm volatile("cp.async.wait_group 0;\n"); }

__device__ __forceinline__ void mma16(float* c, uint32_t a0, uint32_t a1,
                                      uint32_t a2, uint32_t a3,
                                      uint32_t b0, uint32_t b1){
    asm volatile(
        "mma.sync.aligned.m16n8k16.row.col.f32.f16.f16.f32 "
        "{%0,%1,%2,%3}, {%4,%5,%6,%7}, {%8,%9}, {%0,%1,%2,%3};\n"
        : "+f"(c[0]), "+f"(c[1]), "+f"(c[2]), "+f"(c[3])
        : "r"(a0), "r"(a1), "r"(a2), "r"(a3), "r"(b0), "r"(b1));
}

// ---------------- one-shot convert / pack / zero kernel ----------------
#define C_FEAT 131072
#define C_WP   1048576
#define C_WOUT 5120000
#define C_EMB  2560000
#define C_W0I  5242880
#define C_W1I  4194304
#define C_B    1024
#define C_Z    (32768+32768+32768+3+512)
#define CVT_TOTAL (C_FEAT+C_WP+C_WOUT+C_EMB+C_W0I+C_W1I+2*C_B+C_Z)

__global__ void cvt_all(
    const float* __restrict__ features, const float* __restrict__ Wp,
    const float* __restrict__ Wout, const float* __restrict__ emb,
    const float* __restrict__ Wf0, const float* __restrict__ Wi0,
    const float* __restrict__ Wo0, const float* __restrict__ Wg0,
    const float* __restrict__ Wf1, const float* __restrict__ Wi1,
    const float* __restrict__ Wo1, const float* __restrict__ Wg1,
    const float* __restrict__ bf0, const float* __restrict__ bi0,
    const float* __restrict__ bo0, const float* __restrict__ bg0,
    const float* __restrict__ bf1, const float* __restrict__ bi1,
    const float* __restrict__ bo1, const float* __restrict__ bg1)
{
    int i = blockIdx.x*blockDim.x + threadIdx.x;
    if (i >= CVT_TOTAL) return;
    if (i < C_FEAT){
        reinterpret_cast<uint32_t*>(g_featinH)[i] =
            pack2h(features[2*i], features[2*i+1]);
        return;
    }
    i -= C_FEAT;
    if (i < C_WP){
        int pr = i >> 10, n = i & 1023;
        reinterpret_cast<uint32_t*>(g_wbufH + OF_WP)[i] =
            pack2h(Wp[(size_t)(2*pr)*1024 + n], Wp[(size_t)(2*pr+1)*1024 + n]);
        return;
    }
    i -= C_WP;
    if (i < C_WOUT){
        int pr = i / 10000, n = i - pr*10000;
        reinterpret_cast<uint32_t*>(g_wbufH + OF_WOUT)[i] =
            pack2h(Wout[(size_t)(2*pr)*Vv + n], Wout[(size_t)(2*pr+1)*Vv + n]);
        return;
    }
    i -= C_WOUT;
    if (i < C_EMB){
        reinterpret_cast<uint32_t*>(g_wbufH + OF_EMB)[i] =
            pack2h(emb[2*(size_t)i], emb[2*(size_t)i+1]);
        return;
    }
    i -= C_EMB;
    if (i < C_W0I){
        int pr = i >> 12, n = i & 4095;
        int h = n >> 2, gate = n & 3;
        const float* Wx = gate==0?Wf0 : gate==1?Wi0 : gate==2?Wo0 : Wg0;
        reinterpret_cast<uint32_t*>(g_wbufH + OF_W0I)[i] =
            pack2h(Wx[(size_t)(2*pr)*1024 + h], Wx[(size_t)(2*pr+1)*1024 + h]);
        return;
    }
    i -= C_W0I;
    if (i < C_W1I){
        int pr = i >> 12, n = i & 4095;
        int h = n >> 2, gate = n & 3;
        const float* Wx = gate==0?Wf1 : gate==1?Wi1 : gate==2?Wo1 : Wg1;
        reinterpret_cast<uint32_t*>(g_wbufH + OF_W1I)[i] =
            pack2h(Wx[(size_t)(2*pr)*1024 + h], Wx[(size_t)(2*pr+1)*1024 + h]);
        return;
    }
    i -= C_W1I;
    if (i < C_B){
        float4 v; v.x=bf0[i]; v.y=bi0[i]; v.z=bo0[i]; v.w=bg0[i];
        reinterpret_cast<float4*>(g_bias0i)[i] = v; return;
    }
    i -= C_B;
    if (i < C_B){
        float4 v; v.x=bf1[i]; v.y=bi1[i]; v.z=bo1[i]; v.w=bg1[i];
        reinterpret_cast<float4*>(g_bias1i)[i] = v; return;
    }
    i -= C_B;
    {
        float4 z = make_float4(0.f,0.f,0.f,0.f);
        if (i < 32768){ reinterpret_cast<float4*>(g_c0)[i] = z; return; }
        i -= 32768;
        if (i < 32768){ reinterpret_cast<float4*>(g_c1)[i] = z; return; }
        i -= 32768;
        if (i < 32768){ reinterpret_cast<float4*>(g_comb1H)[i] = z; return; }
        i -= 32768;
        if (i == 0){ g_barc = 0u; return; }
        if (i == 1){ g_hbar = 0u; return; }
        if (i == 2) return;
        g_bgrp[i-3] = 0u;
    }
}

// ---------------- 128x128x16 FP16 HMMA GEMM body (head/pre0/out) ----------
#define MODE_LEAKY 1
#define MODE_REMAP 4

struct SmemGemmH {
    uint32_t As[4][128][12];   // 8 k-pairs + pad4
    uint32_t Ws[4][8][136];    // 8 pair-rows x 128 cols + pad8
};

__device__ __forceinline__ void gemm128h_body(
    const __half* __restrict__ A, int lda, int nk,
    const uint32_t* __restrict__ Wq, int ldw,
    const float* __restrict__ bias, const float* __restrict__ rowext,
    float* __restrict__ Cf, __half* __restrict__ Ch, int ldc, int N, int mode,
    int n0, int m0,
    const int* __restrict__ gtok, const __half* __restrict__ embH,
    SmemGemmH& s)
{
    const int tid  = threadIdx.x;
    const int lane = tid & 31, warp = tid >> 5;
    const int wm = warp & 3, wn = warp >> 2;       // warp tile 32 x 64
    const int g  = lane >> 2, tg = lane & 3;

    const int ar = tid >> 1, acq = tid & 1;        // A fill: 128 rows x 2 chunks
    const int wr = tid >> 5;                       // W fill: 8 rows x 32 chunks
    const int wcc = lane * 4;
    const bool wpred = (n0 + wcc) < N;
    const __half* asrc;
    if (gtok){
        int t = m0 >> 7;
        int tok = gtok[ar*Tt + t];
        asrc = embH + (size_t)tok*Ee + acq*8;
    } else {
        asrc = A + (size_t)(m0+ar)*lda + acq*8;
    }
    const uint32_t* wsrc = Wq + (size_t)wr*ldw + n0 + wcc;

    float acc[2][8][4];
    #pragma unroll
    for (int mi=0;mi<2;mi++)
        #pragma unroll
        for (int ni=0;ni<8;ni++)
            #pragma unroll
            for (int j=0;j<4;j++) acc[mi][ni][j]=0.f;

    #pragma unroll
    for (int st2=0; st2<3; ++st2){
        cp16 (&s.As[st2][ar][acq*4], asrc + st2*16);
        cp16p(&s.Ws[st2][wr][wcc], wpred ? (const void*)(wsrc + (size_t)(st2*8)*ldw)
                                         : (const void*)Wq, wpred);
        cp_commit();
    }

    for (int kt=0; kt<nk; ++kt){
        cp_wait2();
        __syncthreads();
        int kn = kt + 3;
        if (kn < nk){
            int sn = kn & 3;
            cp16 (&s.As[sn][ar][acq*4], asrc + kn*16);
            cp16p(&s.Ws[sn][wr][wcc], wpred ? (const void*)(wsrc + (size_t)(kn*8)*ldw)
                                            : (const void*)Wq, wpred);
        }
        cp_commit();
        const int st = kt & 3;
        uint32_t af[2][4];
        #pragma unroll
        for (int mi=0; mi<2; ++mi){
            const int rr = wm*32 + mi*16 + g;
            af[mi][0] = s.As[st][rr  ][tg  ];
            af[mi][1] = s.As[st][rr+8][tg  ];
            af[mi][2] = s.As[st][rr  ][tg+4];
            af[mi][3] = s.As[st][rr+8][tg+4];
        }
        #pragma unroll
        for (int ni=0; ni<8; ++ni){
            const int nc = wn*64 + ni*8 + g;
            uint32_t b0 = s.Ws[st][tg  ][nc];
            uint32_t b1 = s.Ws[st][tg+4][nc];
            mma16(acc[0][ni], af[0][0],af[0][1],af[0][2],af[0][3], b0,b1);
            mma16(acc[1][ni], af[1][0],af[1][1],af[1][2],af[1][3], b0,b1);
        }
    }
    cp_wait0();
    __syncthreads();

    #pragma unroll
    for (int mi=0; mi<2; ++mi){
        const int grow0 = m0 + wm*32 + mi*16 + g;
        const int grow1 = grow0 + 8;
        size_t drow0, drow1;
        if (mode & MODE_REMAP){
            drow0 = (size_t)((grow0 & 127)*Tt + (grow0 >> 7));
            drow1 = (size_t)((grow1 & 127)*Tt + (grow1 >> 7));
        } else { drow0 = (size_t)grow0; drow1 = (size_t)grow1; }
        #pragma unroll
        for (int ni=0; ni<8; ++ni){
            const int gcol = n0 + wn*64 + ni*8 + 2*tg;
            if (gcol >= N) continue;
            float v00=acc[mi][ni][0], v01=acc[mi][ni][1];
            float v10=acc[mi][ni][2], v11=acc[mi][ni][3];
            if (bias){
                float b0v = bias[gcol], b1v = bias[gcol+1];
                v00+=b0v; v01+=b1v; v10+=b0v; v11+=b1v;
            }
            if (rowext){
                const float* r0 = rowext + (size_t)(grow0 & 127)*4096;
                const float* r1 = rowext + (size_t)(grow1 & 127)*4096;
                v00 += r0[gcol]; v01 += r0[gcol+1];
                v10 += r1[gcol]; v11 += r1[gcol+1];
            }
            if (mode & MODE_LEAKY){
                v00 = v00 > 0.f ? v00 : 0.01f*v00;
                v01 = v01 > 0.f ? v01 : 0.01f*v01;
                v10 = v10 > 0.f ? v10 : 0.01f*v10;
                v11 = v11 > 0.f ? v11 : 0.01f*v11;
            }
            if (Ch){
                *reinterpret_cast<uint32_t*>(Ch + drow0*ldc + gcol) = pack2h(v00, v01);
                *reinterpret_cast<uint32_t*>(Ch + drow1*ldc + gcol) = pack2h(v10, v11);
            } else {
                float* C0 = Cf + drow0*ldc;
                float* C1 = Cf + drow1*ldc;
                C0[gcol] = v00; C0[gcol+1] = v01;
                C1[gcol] = v10; C1[gcol+1] = v11;
            }
        }
    }
}

__global__ __launch_bounds__(256) void gemm128h(
    const __half* __restrict__ A, int lda, int nk,
    const uint32_t* __restrict__ Wq, int ldw,
    const float* __restrict__ bias, const float* __restrict__ rowext,
    float* __restrict__ Cf, __half* __restrict__ Ch, int ldc, int N, int mode,
    const int* __restrict__ gtok, const __half* __restrict__ embH)
{
    __shared__ SmemGemmH s;
    gemm128h_body(A, lda, nk, Wq, ldw, bias, rowext, Cf, Ch, ldc, N, mode,
                  blockIdx.x*128, blockIdx.y*128, gtok, embH, s);
}

__global__ __launch_bounds__(256) void head_kernel(const float* __restrict__ bp)
{
    __shared__ SmemGemmH s;
    const int cta = blockIdx.x;
    if (cta < 8){
        gemm128h_body(g_featinH, Ff, 128,
                      reinterpret_cast<const uint32_t*>(g_wbufH + OF_WP), 1024,
                      bp, nullptr, nullptr, g_featH, Hh, Hh, MODE_LEAKY,
                      cta*128, 0, nullptr, nullptr, s);
    }
    __syncthreads();
    if (threadIdx.x == 0){
        __threadfence();
        atomicAdd(&g_hbar, 1u);
        unsigned v;
        do {
            asm volatile("ld.acquire.gpu.u32 %0, [%1];" : "=r"(v) : "l"(&g_hbar) : "memory");
            if (v < 40u) __nanosleep(200);
        } while (v < 40u);
    }
    __syncthreads();
    if (cta >= 8){
        gemm128h_body(g_featH, Hh, 64,
                      reinterpret_cast<const uint32_t*>(g_wbufH + OF_W0I) + (size_t)256*4096, 4096,
                      g_bias0i, nullptr, g_prefeat, nullptr, 4096, 1<<30, 0,
                      (cta-8)*128, 0, nullptr, nullptr, s);
    }
}

// ---------------- persistent recurrence (fp16 operands) ----------------
#define NCTA 256u

__device__ __forceinline__ void gridbar(unsigned &ep, int cta){
    __syncthreads();
    ep += 1;
    if (threadIdx.x == 0){
        __threadfence();
        const int grp = cta >> 5;
        unsigned* gc = &g_bgrp[grp*64];
        atomicAdd(gc, 1u);
        unsigned v;
        if ((cta & 31) == 0){
            do {
                asm volatile("ld.acquire.gpu.u32 %0, [%1];" : "=r"(v) : "l"(gc) : "memory");
                if (v < ep*32u) __nanosleep(128);
            } while (v < ep*32u);
            __threadfence();
            atomicAdd(&g_barc, 1u);
        }
        do {
            asm volatile("ld.acquire.gpu.u32 %0, [%1];" : "=r"(v) : "l"(&g_barc) : "memory");
            if (v < ep*8u) __nanosleep(128);
        } while (v < ep*8u);
    }
    __syncthreads();
}

// 64x64 tile, BK=16 (8 pairs), 4-stage. nk = K/16.
__device__ __forceinline__ void gemm_tile_h(
    const __half* __restrict__ A, int lda,
    const uint32_t* __restrict__ Wq, int ldw,
    int m0, int n0, int nk,
    uint32_t (&As)[4][64][12], uint32_t (&Ws)[4][8][72],
    float acc[4][4])
{
    const int tid  = threadIdx.x;
    const int lane = tid & 31, warp = tid >> 5;
    const int wm = warp & 3, wn = warp >> 2;
    const int g  = lane >> 2, tg = lane & 3;
    const bool isA = tid < 128;
    const int u = tid & 127;
    const int ar = u >> 1, acq = u & 1;            // A: 64 rows x 2 chunks
    const int wr = u >> 4, wc = (u & 15) * 4;      // W: 8 rows x 16 chunks
    const __half* asrc = A + (size_t)(m0+ar)*lda + acq*8;
    const uint32_t* wsrc = Wq + (size_t)wr*ldw + n0 + wc;

    #pragma unroll
    for (int i=0;i<4;i++){
        #pragma unroll
        for (int j=0;j<4;j++) acc[i][j]=0.f;
    }

    #pragma unroll
    for (int st2=0; st2<3; ++st2){
        if (isA) cp16(&As[st2][ar][acq*4], asrc + st2*16);
        else     cp16(&Ws[st2][wr][wc], wsrc + (size_t)(st2*8)*ldw);
        cp_commit();
    }
    for (int kt=0; kt<nk; ++kt){
        cp_wait2();
        __syncthreads();
        int kn = kt + 3;
        if (kn < nk){
            int sn = kn & 3;
            if (isA) cp16(&As[sn][ar][acq*4], asrc + kn*16);
            else     cp16(&Ws[sn][wr][wc], wsrc + (size_t)(kn*8)*ldw);
        }
        cp_commit();
        const int st = kt & 3;
        const int rr = wm*16 + g;
        uint32_t a0 = As[st][rr  ][tg  ];
        uint32_t a1 = As[st][rr+8][tg  ];
        uint32_t a2 = As[st][rr  ][tg+4];
        uint32_t a3 = As[st][rr+8][tg+4];
        #pragma unroll
        for (int ni=0; ni<4; ++ni){
            const int nc = wn*32 + ni*8 + g;
            uint32_t b0 = Ws[st][tg  ][nc];
            uint32_t b1 = Ws[st][tg+4][nc];
            mma16(acc[ni], a0,a1,a2,a3, b0,b1);
        }
    }
    cp_wait0();
    __syncthreads();
}

__device__ __forceinline__ void store_partial(float acc[4][4], int tile,
                                              int wm, int wn, int g, int tg)
{
    float* gp = g_part + (size_t)tile*4096;
    const int lr0 = wm*16 + g, lr1 = lr0 + 8;
    #pragma unroll
    for (int ni=0; ni<4; ++ni){
        const int lc = wn*32 + ni*8 + 2*tg;
        gp[lr0*64 + lc]   = acc[ni][0];
        gp[lr0*64 + lc+1] = acc[ni][1];
        gp[lr1*64 + lc]   = acc[ni][2];
        gp[lr1*64 + lc+1] = acc[ni][3];
    }
}

__device__ __forceinline__ void lstm_epi(float acc[4][4], int tile, int t,
    const float* rowext, const float* colext,
    float* cbuf, int hoff, bool write_hs,
    int m0, int n0, int nb, int wm, int wn, int g, int tg)
{
    const float* gp = g_part + (size_t)tile*4096;
    const int lr0 = wm*16 + g, lr1 = lr0 + 8;
    const int grow0 = m0 + lr0, grow1 = m0 + lr1;
    #pragma unroll
    for (int ni=0; ni<4; ++ni){
        const int lc = wn*32 + ni*8 + 2*tg;
        const int gcol = n0 + lc;
        float v00 = acc[ni][0] + gp[lr0*64 + lc];
        float v01 = acc[ni][1] + gp[lr0*64 + lc+1];
        float v10 = acc[ni][2] + gp[lr1*64 + lc];
        float v11 = acc[ni][3] + gp[lr1*64 + lc+1];
        if (rowext){
            v00 += rowext[(size_t)grow0*4096 + gcol];
            v01 += rowext[(size_t)grow0*4096 + gcol+1];
            v10 += rowext[(size_t)grow1*4096 + gcol];
            v11 += rowext[(size_t)grow1*4096 + gcol+1];
        } else {
            float b0 = colext[gcol], b1 = colext[gcol+1];
            v00+=b0; v01+=b1; v10+=b0; v11+=b1;
        }
        float p00 = __shfl_xor_sync(0xffffffffu, v00, 1);
        float p01 = __shfl_xor_sync(0xffffffffu, v01, 1);
        float p10 = __shfl_xor_sync(0xffffffffu, v10, 1);
        float p11 = __shfl_xor_sync(0xffffffffu, v11, 1);
        if ((tg & 1) == 0){
            const int h = nb*16 + wn*8 + ni*2 + (tg >> 1);
            {
                float f = sigf(v00), ii = sigf(v01);
                float o = sigf(p00), gg = tanhf(p01);
                float c = f*cbuf[grow0*1024 + h] + ii*gg;
                cbuf[grow0*1024 + h] = c;
                __half hn = __float2half_rn(o * tanhf(c));
                g_comb1H[grow0*2048 + hoff + h] = hn;
                if (write_hs) g_hsH[(size_t)t*(Bb*Hh) + grow0*1024 + h] = hn;
            }
            {
                float f = sigf(v10), ii = sigf(v11);
                float o = sigf(p10), gg = tanhf(p11);
                float c = f*cbuf[grow1*1024 + h] + ii*gg;
                cbuf[grow1*1024 + h] = c;
                __half hn = __float2half_rn(o * tanhf(c));
                g_comb1H[grow1*2048 + hoff + h] = hn;
                if (write_hs) g_hsH[(size_t)t*(Bb*Hh) + grow1*1024 + h] = hn;
            }
        }
    }
}

__global__ __launch_bounds__(256, 2) void lstm_persistent()
{
    __shared__ uint32_t As[4][64][12];
    __shared__ uint32_t Ws[4][8][72];

    const int cta  = blockIdx.x;
    const int ks   = cta & 1;
    const int tile = cta >> 1;
    const int mb   = tile & 1, nb = tile >> 1;
    const int m0   = mb*64,   n0 = nb*64;
    const int tid  = threadIdx.x;
    const int lane = tid & 31, warp = tid >> 5;
    const int wm = warp & 3, wn = warp >> 2;
    const int g  = lane >> 2, tg = lane & 3;

    // L0 recurrent: W0I pairs [768 + ks*256, +256), A = comb1H[:, ks*512 ...]
    const uint32_t* W0q = reinterpret_cast<const uint32_t*>(g_wbufH + OF_W0I)
                        + (size_t)(768 + ks*256)*4096;
    const __half*   A0  = g_comb1H + ks*512;
    // L1: W1I pairs [ks*512, +512), A = comb1H[:, ks*1024 ...]
    const uint32_t* W1q = reinterpret_cast<const uint32_t*>(g_wbufH + OF_W1I)
                        + (size_t)(ks*512)*4096;
    const __half*   A1  = g_comb1H + ks*1024;

    unsigned ep = 0;
    float acc[4][4];

    for (int t = 0; t < Tt; ++t){
        gemm_tile_h(A0, 2048, W0q, 4096, m0, n0, 32, As, Ws, acc);
        if (ks == 1) store_partial(acc, tile, wm, wn, g, tg);
        gridbar(ep, cta);
        if (ks == 0)
            lstm_epi(acc, tile, t, g_pre0 + (size_t)t*(Bb*4096), nullptr,
                     g_c0, 0, false, m0, n0, nb, wm, wn, g, tg);
        gridbar(ep, cta);
        gemm_tile_h(A1, 2048, W1q, 4096, m0, n0, 64, As, Ws, acc);
        if (ks == 1) store_partial(acc, tile, wm, wn, g, tg);
        gridbar(ep, cta);
        if (ks == 0)
            lstm_epi(acc, tile, t, nullptr, g_bias1i,
                     g_c1, 1024, true, m0, n0, nb, wm, wn, g, tg);
        gridbar(ep, cta);
    }
}

// ---------------- host orchestration ----------------
extern "C" void kernel_launch(void* const* d_in, const int* in_sizes, int n_in,
                              void* d_out, int out_size)
{
    const int*   tokens    = (const int*)  d_in[0];
    const float* features  = (const float*)d_in[1];
    const float* embedding = (const float*)d_in[2];
    const float* Wp  = (const float*)d_in[3];
    const float* bp  = (const float*)d_in[4];
    const float* Wf0 = (const float*)d_in[5];  const float* bf0 = (const float*)d_in[6];
    const float* Wi0 = (const float*)d_in[7];  const float* bi0 = (const float*)d_in[8];
    const float* Wo0 = (const float*)d_in[9];  const float* bo0 = (const float*)d_in[10];
    const float* Wg0 = (const float*)d_in[11]; const float* bg0 = (const float*)d_in[12];
    const float* Wf1 = (const float*)d_in[13]; const float* bf1 = (const float*)d_in[14];
    const float* Wi1 = (const float*)d_in[15]; const float* bi1 = (const float*)d_in[16];
    const float* Wo1 = (const float*)d_in[17]; const float* bo1 = (const float*)d_in[18];
    const float* Wg1 = (const float*)d_in[19]; const float* bg1 = (const float*)d_in[20];
    const float* Wout = (const float*)d_in[21];
    const float* bout = (const float*)d_in[22];
    float* out = (float*)d_out;

    __half *wbh, *hsh;
    float *pre0, *prefeat;
    cudaGetSymbolAddress((void**)&wbh,     g_wbufH);
    cudaGetSymbolAddress((void**)&hsh,     g_hsH);
    cudaGetSymbolAddress((void**)&pre0,    g_pre0);
    cudaGetSymbolAddress((void**)&prefeat, g_prefeat);

    // 1) convert + pack (fp16) + zero
    cvt_all<<<(CVT_TOTAL + 255)/256, 256>>>(features, Wp, Wout, embedding,
        Wf0, Wi0, Wo0, Wg0, Wf1, Wi1, Wo1, Wg1,
        bf0, bi0, bo0, bg0, bf1, bi1, bo1, bg1);

    // 2) head: feat projection + prefeat (fused, internal barrier)
    head_kernel<<<40, 256>>>(bp);

    // 3) pre0 = gather(embH) @ W0I[pairs 0:256] + prefeat
    gemm128h<<<dim3(32,25), 256>>>(nullptr, 0, 32,
        reinterpret_cast<const uint32_t*>(wbh + OF_W0I), 4096,
        nullptr, prefeat, pre0, nullptr, 4096, 1<<30, 0,
        tokens, wbh + OF_EMB);

    // 4) persistent 25-step recurrence (fp16)   <-- profiled slot
    lstm_persistent<<<NCTA, 256>>>();

    // 5) logits = hsH @ WoutPacked + bout, remap to [B,T,V]
    gemm128h<<<dim3(79,25), 256>>>(hsh, Hh, 64,
        reinterpret_cast<const uint32_t*>(wbh + OF_WOUT), Vv,
        bout, nullptr, out, nullptr, Vv, Vv, MODE_REMAP,
        nullptr, nullptr);
}

// round 17
// speedup vs baseline: 1.5495x; 1.0617x over previous
#include <cuda_runtime.h>
#include <cuda_fp16.h>
#include <cstdint>
#include <math.h>

#define Bb 128
#define Tt 25
#define Ee 512
#define Hh 1024
#define Vv 10000
#define Ff 2048

// ---------------- device scratch ----------------
__device__ __align__(16) __half g_wbufH[36331520]; // fp16 weights(+emb), k-pair packed
__device__ __align__(16) __half g_featinH[Bb*Ff];
__device__ __align__(16) __half g_featH[Bb*Hh];
__device__ __align__(16) __half g_comb1H[Bb*2048];  // [h0 | h1]
__device__ __align__(16) __half g_hsH[Tt*Bb*Hh];
__device__ float g_prefeat[Bb*4096];
__device__ float g_pre0[Tt*Bb*4096];
__device__ float g_c0[Bb*Hh];
__device__ float g_c1[Bb*Hh];
__device__ float g_part[128*4096];
__device__ float g_bias0i[4096];
__device__ float g_bias1i[4096];
__device__ unsigned g_bgrp[8*64];
__device__ unsigned g_barc;
__device__ unsigned g_hbar;

// wbufH offsets (halves; all even)
#define OF_WP   0            /* packed 1024x1024 u32  */
#define OF_W0I  2097152      /* packed 1280x4096 u32  */
#define OF_W1I  12582912     /* packed 1024x4096 u32  */
#define OF_WOUT 20971520     /* packed  512x10000 u32 */
#define OF_EMB  31211520     /* row-major half 10000x512 */

__device__ __forceinline__ float sigf(float x){ return 1.0f/(1.0f + expf(-x)); }
__device__ __forceinline__ uint32_t pack2h(float a, float b){
    uint32_t lo = (uint32_t)__half_as_ushort(__float2half_rn(a));
    uint32_t hi = (uint32_t)__half_as_ushort(__float2half_rn(b));
    return lo | (hi << 16);
}

__device__ __forceinline__ void cp16(void* sdst, const void* gsrc){
    uint32_t s = (uint32_t)__cvta_generic_to_shared(sdst);
    asm volatile("cp.async.cg.shared.global [%0], [%1], 16;\n" :: "r"(s), "l"(gsrc));
}
__device__ __forceinline__ void cp16p(void* sdst, const void* gsrc, bool pred){
    uint32_t s = (uint32_t)__cvta_generic_to_shared(sdst);
    int sz = pred ? 16 : 0;
    asm volatile("cp.async.cg.shared.global [%0], [%1], 16, %2;\n" :: "r"(s), "l"(gsrc), "r"(sz));
}
__device__ __forceinline__ void cp_commit(){ asm volatile("cp.async.commit_group;\n"); }
__device__ __forceinline__ void cp_wait2(){ asm volatile("cp.async.wait_group 2;\n"); }
__device__ __forceinline__ void cp_wait0(){ asm volatile("cp.async.wait_group 0;\n"); }

__device__ __forceinline__ void mma16(float* c, uint32_t a0, uint32_t a1,
                                      uint32_t a2, uint32_t a3,
                                      uint32_t b0, uint32_t b1){
    asm volatile(
        "mma.sync.aligned.m16n8k16.row.col.f32.f16.f16.f32 "
        "{%0,%1,%2,%3}, {%4,%5,%6,%7}, {%8,%9}, {%0,%1,%2,%3};\n"
        : "+f"(c[0]), "+f"(c[1]), "+f"(c[2]), "+f"(c[3])
        : "r"(a0), "r"(a1), "r"(a2), "r"(a3), "r"(b0), "r"(b1));
}

// ---------------- one-shot convert / pack / zero kernel ----------------
#define C_FEAT 131072
#define C_WP   1048576
#define C_WOUT 5120000
#define C_EMB  2560000
#define C_W0I  5242880
#define C_W1I  4194304
#define C_B    1024
#define C_Z    (32768+32768+32768+3+512)
#define CVT_TOTAL (C_FEAT+C_WP+C_WOUT+C_EMB+C_W0I+C_W1I+2*C_B+C_Z)

__global__ void cvt_all(
    const float* __restrict__ features, const float* __restrict__ Wp,
    const float* __restrict__ Wout, const float* __restrict__ emb,
    const float* __restrict__ Wf0, const float* __restrict__ Wi0,
    const float* __restrict__ Wo0, const float* __restrict__ Wg0,
    const float* __restrict__ Wf1, const float* __restrict__ Wi1,
    const float* __restrict__ Wo1, const float* __restrict__ Wg1,
    const float* __restrict__ bf0, const float* __restrict__ bi0,
    const float* __restrict__ bo0, const float* __restrict__ bg0,
    const float* __restrict__ bf1, const float* __restrict__ bi1,
    const float* __restrict__ bo1, const float* __restrict__ bg1)
{
    int i = blockIdx.x*blockDim.x + threadIdx.x;
    if (i >= CVT_TOTAL) return;
    if (i < C_FEAT){
        reinterpret_cast<uint32_t*>(g_featinH)[i] =
            pack2h(features[2*i], features[2*i+1]);
        return;
    }
    i -= C_FEAT;
    if (i < C_WP){
        int pr = i >> 10, n = i & 1023;
        reinterpret_cast<uint32_t*>(g_wbufH + OF_WP)[i] =
            pack2h(Wp[(size_t)(2*pr)*1024 + n], Wp[(size_t)(2*pr+1)*1024 + n]);
        return;
    }
    i -= C_WP;
    if (i < C_WOUT){
        int pr = i / 10000, n = i - pr*10000;
        reinterpret_cast<uint32_t*>(g_wbufH + OF_WOUT)[i] =
            pack2h(Wout[(size_t)(2*pr)*Vv + n], Wout[(size_t)(2*pr+1)*Vv + n]);
        return;
    }
    i -= C_WOUT;
    if (i < C_EMB){
        reinterpret_cast<uint32_t*>(g_wbufH + OF_EMB)[i] =
            pack2h(emb[2*(size_t)i], emb[2*(size_t)i+1]);
        return;
    }
    i -= C_EMB;
    if (i < C_W0I){
        int pr = i >> 12, n = i & 4095;
        int h = n >> 2, gate = n & 3;
        const float* Wx = gate==0?Wf0 : gate==1?Wi0 : gate==2?Wo0 : Wg0;
        reinterpret_cast<uint32_t*>(g_wbufH + OF_W0I)[i] =
            pack2h(Wx[(size_t)(2*pr)*1024 + h], Wx[(size_t)(2*pr+1)*1024 + h]);
        return;
    }
    i -= C_W0I;
    if (i < C_W1I){
        int pr = i >> 12, n = i & 4095;
        int h = n >> 2, gate = n & 3;
        const float* Wx = gate==0?Wf1 : gate==1?Wi1 : gate==2?Wo1 : Wg1;
        reinterpret_cast<uint32_t*>(g_wbufH + OF_W1I)[i] =
            pack2h(Wx[(size_t)(2*pr)*1024 + h], Wx[(size_t)(2*pr+1)*1024 + h]);
        return;
    }
    i -= C_W1I;
    if (i < C_B){
        float4 v; v.x=bf0[i]; v.y=bi0[i]; v.z=bo0[i]; v.w=bg0[i];
        reinterpret_cast<float4*>(g_bias0i)[i] = v; return;
    }
    i -= C_B;
    if (i < C_B){
        float4 v; v.x=bf1[i]; v.y=bi1[i]; v.z=bo1[i]; v.w=bg1[i];
        reinterpret_cast<float4*>(g_bias1i)[i] = v; return;
    }
    i -= C_B;
    {
        float4 z = make_float4(0.f,0.f,0.f,0.f);
        if (i < 32768){ reinterpret_cast<float4*>(g_c0)[i] = z; return; }
        i -= 32768;
        if (i < 32768){ reinterpret_cast<float4*>(g_c1)[i] = z; return; }
        i -= 32768;
        if (i < 32768){ reinterpret_cast<float4*>(g_comb1H)[i] = z; return; }
        i -= 32768;
        if (i == 0){ g_barc = 0u; return; }
        if (i == 1){ g_hbar = 0u; return; }
        if (i == 2) return;
        g_bgrp[i-3] = 0u;
    }
}

// ---------------- 128x128x16 FP16 HMMA GEMM body (head/pre0/out) ----------
#define MODE_LEAKY 1
#define MODE_REMAP 4

struct SmemGemmH {
    uint32_t As[4][128][12];   // 8 k-pairs + pad4
    uint32_t Ws[4][8][136];    // 8 pair-rows x 128 cols + pad8
};

__device__ __forceinline__ void gemm128h_body(
    const __half* __restrict__ A, int lda, int nk,
    const uint32_t* __restrict__ Wq, int ldw,
    const float* __restrict__ bias, const float* __restrict__ rowext,
    float* __restrict__ Cf, __half* __restrict__ Ch, int ldc, int N, int mode,
    int n0, int m0,
    const int* __restrict__ gtok, const __half* __restrict__ embH,
    SmemGemmH& s)
{
    const int tid  = threadIdx.x;
    const int lane = tid & 31, warp = tid >> 5;
    const int wm = warp & 3, wn = warp >> 2;       // warp tile 32 x 64
    const int g  = lane >> 2, tg = lane & 3;

    const int ar = tid >> 1, acq = tid & 1;
    const int wr = tid >> 5;
    const int wcc = lane * 4;
    const bool wpred = (n0 + wcc) < N;
    const __half* asrc;
    if (gtok){
        int t = m0 >> 7;
        int tok = gtok[ar*Tt + t];
        asrc = embH + (size_t)tok*Ee + acq*8;
    } else {
        asrc = A + (size_t)(m0+ar)*lda + acq*8;
    }
    const uint32_t* wsrc = Wq + (size_t)wr*ldw + n0 + wcc;

    float acc[2][8][4];
    #pragma unroll
    for (int mi=0;mi<2;mi++)
        #pragma unroll
        for (int ni=0;ni<8;ni++)
            #pragma unroll
            for (int j=0;j<4;j++) acc[mi][ni][j]=0.f;

    #pragma unroll
    for (int st2=0; st2<3; ++st2){
        cp16 (&s.As[st2][ar][acq*4], asrc + st2*16);
        cp16p(&s.Ws[st2][wr][wcc], wpred ? (const void*)(wsrc + (size_t)(st2*8)*ldw)
                                         : (const void*)Wq, wpred);
        cp_commit();
    }

    for (int kt=0; kt<nk; ++kt){
        cp_wait2();
        __syncthreads();
        int kn = kt + 3;
        if (kn < nk){
            int sn = kn & 3;
            cp16 (&s.As[sn][ar][acq*4], asrc + kn*16);
            cp16p(&s.Ws[sn][wr][wcc], wpred ? (const void*)(wsrc + (size_t)(kn*8)*ldw)
                                            : (const void*)Wq, wpred);
        }
        cp_commit();
        const int st = kt & 3;
        uint32_t af[2][4];
        #pragma unroll
        for (int mi=0; mi<2; ++mi){
            const int rr = wm*32 + mi*16 + g;
            af[mi][0] = s.As[st][rr  ][tg  ];
            af[mi][1] = s.As[st][rr+8][tg  ];
            af[mi][2] = s.As[st][rr  ][tg+4];
            af[mi][3] = s.As[st][rr+8][tg+4];
        }
        #pragma unroll
        for (int ni=0; ni<8; ++ni){
            const int nc = wn*64 + ni*8 + g;
            uint32_t b0 = s.Ws[st][tg  ][nc];
            uint32_t b1 = s.Ws[st][tg+4][nc];
            mma16(acc[0][ni], af[0][0],af[0][1],af[0][2],af[0][3], b0,b1);
            mma16(acc[1][ni], af[1][0],af[1][1],af[1][2],af[1][3], b0,b1);
        }
    }
    cp_wait0();
    __syncthreads();

    #pragma unroll
    for (int mi=0; mi<2; ++mi){
        const int grow0 = m0 + wm*32 + mi*16 + g;
        const int grow1 = grow0 + 8;
        size_t drow0, drow1;
        if (mode & MODE_REMAP){
            drow0 = (size_t)((grow0 & 127)*Tt + (grow0 >> 7));
            drow1 = (size_t)((grow1 & 127)*Tt + (grow1 >> 7));
        } else { drow0 = (size_t)grow0; drow1 = (size_t)grow1; }
        #pragma unroll
        for (int ni=0; ni<8; ++ni){
            const int gcol = n0 + wn*64 + ni*8 + 2*tg;
            if (gcol >= N) continue;
            float v00=acc[mi][ni][0], v01=acc[mi][ni][1];
            float v10=acc[mi][ni][2], v11=acc[mi][ni][3];
            if (bias){
                float b0v = bias[gcol], b1v = bias[gcol+1];
                v00+=b0v; v01+=b1v; v10+=b0v; v11+=b1v;
            }
            if (rowext){
                const float* r0 = rowext + (size_t)(grow0 & 127)*4096;
                const float* r1 = rowext + (size_t)(grow1 & 127)*4096;
                v00 += r0[gcol]; v01 += r0[gcol+1];
                v10 += r1[gcol]; v11 += r1[gcol+1];
            }
            if (mode & MODE_LEAKY){
                v00 = v00 > 0.f ? v00 : 0.01f*v00;
                v01 = v01 > 0.f ? v01 : 0.01f*v01;
                v10 = v10 > 0.f ? v10 : 0.01f*v10;
                v11 = v11 > 0.f ? v11 : 0.01f*v11;
            }
            if (Ch){
                *reinterpret_cast<uint32_t*>(Ch + drow0*ldc + gcol) = pack2h(v00, v01);
                *reinterpret_cast<uint32_t*>(Ch + drow1*ldc + gcol) = pack2h(v10, v11);
            } else {
                float* C0 = Cf + drow0*ldc;
                float* C1 = Cf + drow1*ldc;
                C0[gcol] = v00; C0[gcol+1] = v01;
                C1[gcol] = v10; C1[gcol+1] = v11;
            }
        }
    }
}

__global__ __launch_bounds__(256) void gemm128h(
    const __half* __restrict__ A, int lda, int nk,
    const uint32_t* __restrict__ Wq, int ldw,
    const float* __restrict__ bias, const float* __restrict__ rowext,
    float* __restrict__ Cf, __half* __restrict__ Ch, int ldc, int N, int mode,
    const int* __restrict__ gtok, const __half* __restrict__ embH)
{
    __shared__ SmemGemmH s;
    gemm128h_body(A, lda, nk, Wq, ldw, bias, rowext, Cf, Ch, ldc, N, mode,
                  blockIdx.x*128, blockIdx.y*128, gtok, embH, s);
}

__global__ __launch_bounds__(256) void head_kernel(const float* __restrict__ bp)
{
    __shared__ SmemGemmH s;
    const int cta = blockIdx.x;
    if (cta < 8){
        gemm128h_body(g_featinH, Ff, 128,
                      reinterpret_cast<const uint32_t*>(g_wbufH + OF_WP), 1024,
                      bp, nullptr, nullptr, g_featH, Hh, Hh, MODE_LEAKY,
                      cta*128, 0, nullptr, nullptr, s);
    }
    __syncthreads();
    if (threadIdx.x == 0){
        __threadfence();
        atomicAdd(&g_hbar, 1u);
        unsigned v;
        do {
            asm volatile("ld.acquire.gpu.u32 %0, [%1];" : "=r"(v) : "l"(&g_hbar) : "memory");
            if (v < 40u) __nanosleep(200);
        } while (v < 40u);
    }
    __syncthreads();
    if (cta >= 8){
        gemm128h_body(g_featH, Hh, 64,
                      reinterpret_cast<const uint32_t*>(g_wbufH + OF_W0I) + (size_t)256*4096, 4096,
                      g_bias0i, nullptr, g_prefeat, nullptr, 4096, 1<<30, 0,
                      (cta-8)*128, 0, nullptr, nullptr, s);
    }
}

// ---------------- persistent recurrence (fp16, BK=32, 4-stage) -------------
#define NCTA 256u

__device__ __forceinline__ void gridbar(unsigned &ep, int cta){
    __syncthreads();
    ep += 1;
    if (threadIdx.x == 0){
        __threadfence();
        const int grp = cta >> 5;
        unsigned* gc = &g_bgrp[grp*64];
        atomicAdd(gc, 1u);
        unsigned v;
        if ((cta & 31) == 0){
            do {
                asm volatile("ld.acquire.gpu.u32 %0, [%1];" : "=r"(v) : "l"(gc) : "memory");
                if (v < ep*32u) __nanosleep(128);
            } while (v < ep*32u);
            __threadfence();
            atomicAdd(&g_barc, 1u);
        }
        do {
            asm volatile("ld.acquire.gpu.u32 %0, [%1];" : "=r"(v) : "l"(&g_barc) : "memory");
            if (v < ep*8u) __nanosleep(128);
        } while (v < ep*8u);
    }
    __syncthreads();
}

// 64x64 tile, BK=32 (16 pairs), 4-stage. nk = K/32.
__device__ __forceinline__ void gemm_tile_h32(
    const __half* __restrict__ A, int lda,
    const uint32_t* __restrict__ Wq, int ldw,
    int m0, int n0, int nk,
    uint32_t (&As)[4][64][20], uint32_t (&Ws)[4][16][72],
    float acc[4][4])
{
    const int tid  = threadIdx.x;
    const int lane = tid & 31, warp = tid >> 5;
    const int wm = warp & 3, wn = warp >> 2;
    const int g  = lane >> 2, tg = lane & 3;
    // A: 64 rows x 4 chunks (16B = 4 pairs each) -> 256 chunks, 1/thread
    const int ar = tid >> 2, acq = tid & 3;
    // W: 16 pair-rows x 16 chunks -> 256 chunks, 1/thread
    const int wr = tid >> 4, wc = (tid & 15) * 4;
    const __half* asrc = A + (size_t)(m0+ar)*lda + acq*8;
    const uint32_t* wsrc = Wq + (size_t)wr*ldw + n0 + wc;

    #pragma unroll
    for (int i=0;i<4;i++){
        #pragma unroll
        for (int j=0;j<4;j++) acc[i][j]=0.f;
    }

    #pragma unroll
    for (int st2=0; st2<3; ++st2){
        cp16(&As[st2][ar][acq*4], asrc + st2*32);
        cp16(&Ws[st2][wr][wc], wsrc + (size_t)(st2*16)*ldw);
        cp_commit();
    }
    for (int kt=0; kt<nk; ++kt){
        cp_wait2();
        __syncthreads();
        int kn = kt + 3;
        if (kn < nk){
            int sn = kn & 3;
            cp16(&As[sn][ar][acq*4], asrc + kn*32);
            cp16(&Ws[sn][wr][wc], wsrc + (size_t)(kn*16)*ldw);
        }
        cp_commit();
        const int st = kt & 3;
        const int rr = wm*16 + g;
        #pragma unroll
        for (int kk=0; kk<2; ++kk){
            const int kc = kk*8;
            uint32_t a0 = As[st][rr  ][kc+tg  ];
            uint32_t a1 = As[st][rr+8][kc+tg  ];
            uint32_t a2 = As[st][rr  ][kc+tg+4];
            uint32_t a3 = As[st][rr+8][kc+tg+4];
            #pragma unroll
            for (int ni=0; ni<4; ++ni){
                const int nc = wn*32 + ni*8 + g;
                uint32_t b0 = Ws[st][kc+tg  ][nc];
                uint32_t b1 = Ws[st][kc+tg+4][nc];
                mma16(acc[ni], a0,a1,a2,a3, b0,b1);
            }
        }
    }
    cp_wait0();
    __syncthreads();
}

__device__ __forceinline__ void store_partial(float acc[4][4], int tile,
                                              int wm, int wn, int g, int tg)
{
    float* gp = g_part + (size_t)tile*4096;
    const int lr0 = wm*16 + g, lr1 = lr0 + 8;
    #pragma unroll
    for (int ni=0; ni<4; ++ni){
        const int lc = wn*32 + ni*8 + 2*tg;
        gp[lr0*64 + lc]   = acc[ni][0];
        gp[lr0*64 + lc+1] = acc[ni][1];
        gp[lr1*64 + lc]   = acc[ni][2];
        gp[lr1*64 + lc+1] = acc[ni][3];
    }
}

__device__ __forceinline__ void lstm_epi(float acc[4][4], int tile, int t,
    const float* rowext, const float* colext,
    float* cbuf, int hoff, bool write_hs,
    int m0, int n0, int nb, int wm, int wn, int g, int tg)
{
    const float* gp = g_part + (size_t)tile*4096;
    const int lr0 = wm*16 + g, lr1 = lr0 + 8;
    const int grow0 = m0 + lr0, grow1 = m0 + lr1;
    #pragma unroll
    for (int ni=0; ni<4; ++ni){
        const int lc = wn*32 + ni*8 + 2*tg;
        const int gcol = n0 + lc;
        float v00 = acc[ni][0] + gp[lr0*64 + lc];
        float v01 = acc[ni][1] + gp[lr0*64 + lc+1];
        float v10 = acc[ni][2] + gp[lr1*64 + lc];
        float v11 = acc[ni][3] + gp[lr1*64 + lc+1];
        if (rowext){
            v00 += rowext[(size_t)grow0*4096 + gcol];
            v01 += rowext[(size_t)grow0*4096 + gcol+1];
            v10 += rowext[(size_t)grow1*4096 + gcol];
            v11 += rowext[(size_t)grow1*4096 + gcol+1];
        } else {
            float b0 = colext[gcol], b1 = colext[gcol+1];
            v00+=b0; v01+=b1; v10+=b0; v11+=b1;
        }
        float p00 = __shfl_xor_sync(0xffffffffu, v00, 1);
        float p01 = __shfl_xor_sync(0xffffffffu, v01, 1);
        float p10 = __shfl_xor_sync(0xffffffffu, v10, 1);
        float p11 = __shfl_xor_sync(0xffffffffu, v11, 1);
        if ((tg & 1) == 0){
            const int h = nb*16 + wn*8 + ni*2 + (tg >> 1);
            {
                float f = sigf(v00), ii = sigf(v01);
                float o = sigf(p00), gg = tanhf(p01);
                float c = f*cbuf[grow0*1024 + h] + ii*gg;
                cbuf[grow0*1024 + h] = c;
                __half hn = __float2half_rn(o * tanhf(c));
                g_comb1H[grow0*2048 + hoff + h] = hn;
                if (write_hs) g_hsH[(size_t)t*(Bb*Hh) + grow0*1024 + h] = hn;
            }
            {
                float f = sigf(v10), ii = sigf(v11);
                float o = sigf(p10), gg = tanhf(p11);
                float c = f*cbuf[grow1*1024 + h] + ii*gg;
                cbuf[grow1*1024 + h] = c;
                __half hn = __float2half_rn(o * tanhf(c));
                g_comb1H[grow1*2048 + hoff + h] = hn;
                if (write_hs) g_hsH[(size_t)t*(Bb*Hh) + grow1*1024 + h] = hn;
            }
        }
    }
}

__global__ __launch_bounds__(256, 2) void lstm_persistent()
{
    __shared__ uint32_t As[4][64][20];
    __shared__ uint32_t Ws[4][16][72];

    const int cta  = blockIdx.x;
    const int ks   = cta & 1;
    const int tile = cta >> 1;
    const int mb   = tile & 1, nb = tile >> 1;
    const int m0   = mb*64,   n0 = nb*64;
    const int tid  = threadIdx.x;
    const int lane = tid & 31, warp = tid >> 5;
    const int wm = warp & 3, wn = warp >> 2;
    const int g  = lane >> 2, tg = lane & 3;

    const uint32_t* W0q = reinterpret_cast<const uint32_t*>(g_wbufH + OF_W0I)
                        + (size_t)(768 + ks*256)*4096;
    const __half*   A0  = g_comb1H + ks*512;
    const uint32_t* W1q = reinterpret_cast<const uint32_t*>(g_wbufH + OF_W1I)
                        + (size_t)(ks*512)*4096;
    const __half*   A1  = g_comb1H + ks*1024;

    unsigned ep = 0;
    float acc[4][4];

    for (int t = 0; t < Tt; ++t){
        gemm_tile_h32(A0, 2048, W0q, 4096, m0, n0, 16, As, Ws, acc);
        if (ks == 1) store_partial(acc, tile, wm, wn, g, tg);
        gridbar(ep, cta);
        if (ks == 0)
            lstm_epi(acc, tile, t, g_pre0 + (size_t)t*(Bb*4096), nullptr,
                     g_c0, 0, false, m0, n0, nb, wm, wn, g, tg);
        gridbar(ep, cta);
        gemm_tile_h32(A1, 2048, W1q, 4096, m0, n0, 32, As, Ws, acc);
        if (ks == 1) store_partial(acc, tile, wm, wn, g, tg);
        gridbar(ep, cta);
        if (ks == 0)
            lstm_epi(acc, tile, t, nullptr, g_bias1i,
                     g_c1, 1024, true, m0, n0, nb, wm, wn, g, tg);
        gridbar(ep, cta);
    }
}

// ---------------- host orchestration ----------------
extern "C" void kernel_launch(void* const* d_in, const int* in_sizes, int n_in,
                              void* d_out, int out_size)
{
    const int*   tokens    = (const int*)  d_in[0];
    const float* features  = (const float*)d_in[1];
    const float* embedding = (const float*)d_in[2];
    const float* Wp  = (const float*)d_in[3];
    const float* bp  = (const float*)d_in[4];
    const float* Wf0 = (const float*)d_in[5];  const float* bf0 = (const float*)d_in[6];
    const float* Wi0 = (const float*)d_in[7];  const float* bi0 = (const float*)d_in[8];
    const float* Wo0 = (const float*)d_in[9];  const float* bo0 = (const float*)d_in[10];
    const float* Wg0 = (const float*)d_in[11]; const float* bg0 = (const float*)d_in[12];
    const float* Wf1 = (const float*)d_in[13]; const float* bf1 = (const float*)d_in[14];
    const float* Wi1 = (const float*)d_in[15]; const float* bi1 = (const float*)d_in[16];
    const float* Wo1 = (const float*)d_in[17]; const float* bo1 = (const float*)d_in[18];
    const float* Wg1 = (const float*)d_in[19]; const float* bg1 = (const float*)d_in[20];
    const float* Wout = (const float*)d_in[21];
    const float* bout = (const float*)d_in[22];
    float* out = (float*)d_out;

    __half *wbh, *hsh;
    float *pre0, *prefeat;
    cudaGetSymbolAddress((void**)&wbh,     g_wbufH);
    cudaGetSymbolAddress((void**)&hsh,     g_hsH);
    cudaGetSymbolAddress((void**)&pre0,    g_pre0);
    cudaGetSymbolAddress((void**)&prefeat, g_prefeat);

    // 1) convert + pack (fp16) + zero
    cvt_all<<<(CVT_TOTAL + 255)/256, 256>>>(features, Wp, Wout, embedding,
        Wf0, Wi0, Wo0, Wg0, Wf1, Wi1, Wo1, Wg1,
        bf0, bi0, bo0, bg0, bf1, bi1, bo1, bg1);

    // 2) head: feat projection + prefeat (fused, internal barrier)
    head_kernel<<<40, 256>>>(bp);

    // 3) pre0 = gather(embH) @ W0I[pairs 0:256] + prefeat
    gemm128h<<<dim3(32,25), 256>>>(nullptr, 0, 32,
        reinterpret_cast<const uint32_t*>(wbh + OF_W0I), 4096,
        nullptr, prefeat, pre0, nullptr, 4096, 1<<30, 0,
        tokens, wbh + OF_EMB);

    // 4) persistent 25-step recurrence (fp16, BK=32)   <-- profiled slot
    lstm_persistent<<<NCTA, 256>>>();

    // 5) logits = hsH @ WoutPacked + bout, remap to [B,T,V]
    gemm128h<<<dim3(79,25), 256>>>(hsh, Hh, 64,
        reinterpret_cast<const uint32_t*>(wbh + OF_WOUT), Vv,
        bout, nullptr, out, nullptr, Vv, Vv, MODE_REMAP,
        nullptr, nullptr);
}